// round 1
// baseline (speedup 1.0000x reference)
#include <cuda_runtime.h>
#include <cuda_bf16.h>
#include <math.h>

#define BB   128     // batch
#define TT   200     // timesteps
#define CC   40      // codes per visit
#define NCODE 2000
#define DAUX 16
#define EE   128     // embedding dim
#define GG   512     // 4*E
#define HH   256     // mlp hidden

// ---------------- scratch (static device arrays; no runtime allocation) -----
__device__ float g_x [TT * BB * EE];        // relu(embed), row = t*B + b
__device__ float g_xw[TT * BB * GG];        // x @ W_x + b_lstm
__device__ float g_h [(TT + 1) * BB * EE];  // h history, g_h[0] = zeros
__device__ unsigned g_cnt;                  // barrier counter (self-resetting)
__device__ unsigned g_epoch;                // barrier epoch (monotonic)

// ---------------- kernel A: multi-hot embed + aux + bias + relu -------------
__global__ void embed_kernel(const int* __restrict__ code,
                             const float* __restrict__ aux,
                             const float* __restrict__ Wlin,
                             const float* __restrict__ blin) {
    int bt = blockIdx.x;            // b*T + t
    int b = bt / TT, t = bt % TT;
    __shared__ int   codes[CC];
    __shared__ float flags[CC];
    __shared__ float auxs[DAUX];
    int tid = threadIdx.x;          // 128
    if (tid < CC)   codes[tid] = code[bt * CC + tid];
    if (tid < DAUX) auxs[tid]  = aux[bt * DAUX + tid];
    __syncthreads();
    if (tid < CC) {
        int v = codes[tid];
        float f = (v > 0) ? 1.f : 0.f;
        for (int j = 0; j < tid; j++)
            if (codes[j] == v) f = 0.f;   // binary multi-hot: dedupe
        flags[tid] = f;
    }
    __syncthreads();
    float acc = blin[tid];
    #pragma unroll 4
    for (int c = 0; c < CC; c++) {
        if (flags[c] != 0.f)                       // uniform across block
            acc += Wlin[(codes[c] - 1) * EE + tid];
    }
    #pragma unroll
    for (int k = 0; k < DAUX; k++)
        acc += auxs[k] * Wlin[(NCODE + k) * EE + tid];
    g_x[(t * BB + b) * EE + tid] = fmaxf(acc, 0.f);
}

// ---------------- kernel B: xw = x @ W_x + b_lstm  ([25600,128]@[128,512]) --
// 64x64 tile, K chunked by 64, 256 threads, 4x4 micro-tile.
__global__ void xw_kernel(const float* __restrict__ Wx,
                          const float* __restrict__ blstm) {
    __shared__ float xs[64][65];   // [k][row_local], padded
    __shared__ float ws[64][64];   // [k][col_local]
    int tid = threadIdx.x;
    int row0 = blockIdx.x * 64, col0 = blockIdx.y * 64;
    int ty = tid / 16, tx = tid % 16;
    float acc[4][4];
    #pragma unroll
    for (int i = 0; i < 4; i++)
        #pragma unroll
        for (int j = 0; j < 4; j++) acc[i][j] = 0.f;

    for (int kb = 0; kb < 128; kb += 64) {
        // load x chunk: 64 rows x 64 k
        for (int i = tid; i < 64 * 64; i += 256) {
            int r = i >> 6, k = i & 63;
            xs[k][r] = g_x[(row0 + r) * EE + kb + k];
        }
        // load W chunk: 64 k x 64 cols
        for (int i = tid; i < 64 * 64; i += 256) {
            int k = i >> 6, c = i & 63;
            ws[k][c] = Wx[(kb + k) * GG + col0 + c];
        }
        __syncthreads();
        #pragma unroll 8
        for (int k = 0; k < 64; k++) {
            float a[4], w[4];
            #pragma unroll
            for (int i = 0; i < 4; i++) a[i] = xs[k][ty * 4 + i];
            #pragma unroll
            for (int j = 0; j < 4; j++) w[j] = ws[k][tx * 4 + j];
            #pragma unroll
            for (int i = 0; i < 4; i++)
                #pragma unroll
                for (int j = 0; j < 4; j++)
                    acc[i][j] = fmaf(a[i], w[j], acc[i][j]);
        }
        __syncthreads();
    }
    #pragma unroll
    for (int i = 0; i < 4; i++) {
        int r = row0 + ty * 4 + i;
        #pragma unroll
        for (int j = 0; j < 4; j++) {
            int c = col0 + tx * 4 + j;
            g_xw[r * GG + c] = acc[i][j] + blstm[c];
        }
    }
}

// ---------------- kernel C: persistent LSTM with global barrier -------------
// 128 CTAs = 8 b-groups(16) x 16 e-groups(8). Each CTA computes z columns
// {gate*128 + e0 + el : gate 0..3, el 0..7} (32 cols) for its 16 batch rows.
#define NCTA 128

__device__ __forceinline__ void grid_barrier(unsigned target) {
    __syncthreads();
    if (threadIdx.x == 0) {
        __threadfence();
        unsigned old = atomicAdd(&g_cnt, 1u);
        if (old == NCTA - 1) {
            g_cnt = 0;                       // only this thread is active here
            __threadfence();
            *(volatile unsigned*)&g_epoch = target;   // release
        } else {
            while (*(volatile unsigned*)&g_epoch != target) { }
            __threadfence();
        }
    }
    __syncthreads();
}

__device__ __forceinline__ float sigmoidf_(float x) {
    return 1.f / (1.f + expf(-x));
}

__global__ void __launch_bounds__(256, 1)
lstm_kernel(const float* __restrict__ Wh) {
    int cta = blockIdx.x;
    int bg = cta >> 4;                 // 0..7
    int eg = cta & 15;                 // 0..15
    int b0 = bg * 16, e0 = eg * 8;

    __shared__ float w_sm[128][32];    // [k][cc]  cc = gate*8 + el   (16 KB)
    __shared__ float h_sm[16][128];    // 8 KB
    __shared__ float z_sm[16][32];     // 2 KB
    __shared__ float c_sm[16][8];      // cell state, persists across steps

    int tid = threadIdx.x;
    unsigned base = *(volatile unsigned*)&g_epoch;  // stable until 1st barrier

    // resident W_h slice
    for (int i = tid; i < 128 * 32; i += 256) {
        int k = i >> 5, cc = i & 31;
        int gate = cc >> 3, el = cc & 7;
        w_sm[k][cc] = Wh[k * GG + gate * EE + e0 + el];
    }
    if (tid < 128) c_sm[tid >> 3][tid & 7] = 0.f;
    // cooperative zero of g_h[0]
    {
        int gi = cta * 256 + tid;
        if (gi < BB * EE) g_h[gi] = 0.f;
    }
    unsigned ep = base + 1;
    grid_barrier(ep);

    int bi = tid >> 4, cj = tid & 15;
    int cc0 = cj * 2;
    int gate = cc0 >> 3, el = cc0 & 7;

    for (int t = 0; t < TT; t++) {
        // load h_{t} for our 16 batch rows
        for (int i = tid; i < 16 * 128; i += 256) {
            int r = i >> 7, k = i & 127;
            h_sm[r][k] = g_h[t * BB * EE + (b0 + r) * EE + k];
        }
        __syncthreads();

        const float* xwp = &g_xw[(t * BB + b0 + bi) * GG + gate * EE + e0 + el];
        float acc0 = xwp[0];
        float acc1 = xwp[1];
        const float* hr = h_sm[bi];
        #pragma unroll 8
        for (int k = 0; k < 128; k++) {
            float hv = hr[k];
            acc0 = fmaf(hv, w_sm[k][cc0], acc0);
            acc1 = fmaf(hv, w_sm[k][cc0 + 1], acc1);
        }
        z_sm[bi][cc0]     = acc0;
        z_sm[bi][cc0 + 1] = acc1;
        __syncthreads();

        if (tid < 128) {
            int b2 = tid >> 3, e2 = tid & 7;
            float zi = z_sm[b2][e2];
            float zf = z_sm[b2][8 + e2];
            float zg = z_sm[b2][16 + e2];
            float zo = z_sm[b2][24 + e2];
            float c = sigmoidf_(zf) * c_sm[b2][e2] + sigmoidf_(zi) * tanhf(zg);
            c_sm[b2][e2] = c;
            float h = sigmoidf_(zo) * tanhf(c);
            g_h[(t + 1) * BB * EE + (b0 + b2) * EE + e0 + e2] = h;
        }
        ep++;
        grid_barrier(ep);    // h_{t+1} fully published
    }
}

// ---------------- kernel D: gather last h, MLP, L2-normalize ----------------
__global__ void head_kernel(const int* __restrict__ length,
                            const float* __restrict__ W0,
                            const float* __restrict__ b0v,
                            const float* __restrict__ W1,
                            const float* __restrict__ b1v,
                            float* __restrict__ out) {
    int b = blockIdx.x;             // 128
    int tid = threadIdx.x;          // 256
    __shared__ float hl[EE];
    __shared__ float m[HH];
    __shared__ float red[HH];
    int L = length[b];              // 1..200
    if (tid < EE) hl[tid] = g_h[L * BB * EE + b * EE + tid];
    __syncthreads();
    float a = b0v[tid];
    #pragma unroll 8
    for (int k = 0; k < EE; k++) a = fmaf(hl[k], W0[k * HH + tid], a);
    m[tid] = fmaxf(a, 0.f);
    __syncthreads();
    float f = b1v[tid];
    #pragma unroll 8
    for (int k = 0; k < HH; k++) f = fmaf(m[k], W1[k * HH + tid], f);
    red[tid] = f * f;
    __syncthreads();
    for (int s = 128; s > 0; s >>= 1) {
        if (tid < s) red[tid] += red[tid + s];
        __syncthreads();
    }
    out[b * HH + tid] = f / sqrtf(red[0]);
}

// ---------------- launch -----------------------------------------------------
extern "C" void kernel_launch(void* const* d_in, const int* in_sizes, int n_in,
                              void* d_out, int out_size) {
    const int*   code   = (const int*)  d_in[0];
    const float* aux    = (const float*)d_in[1];
    const int*   length = (const int*)  d_in[2];
    // d_in[3] = is_training (unused, inference)
    const float* Wlin   = (const float*)d_in[4];
    const float* blin   = (const float*)d_in[5];
    const float* Wx     = (const float*)d_in[6];
    const float* Wh     = (const float*)d_in[7];
    const float* blstm  = (const float*)d_in[8];
    const float* W0     = (const float*)d_in[9];
    const float* b0v    = (const float*)d_in[10];
    const float* W1     = (const float*)d_in[11];
    const float* b1v    = (const float*)d_in[12];
    float* out = (float*)d_out;

    embed_kernel<<<BB * TT, 128>>>(code, aux, Wlin, blin);
    dim3 gb(TT * BB / 64, GG / 64);
    xw_kernel<<<gb, 256>>>(Wx, blstm);
    lstm_kernel<<<NCTA, 256>>>(Wh);
    head_kernel<<<BB, 256>>>(length, W0, b0v, W1, b1v, out);
}

// round 2
// speedup vs baseline: 1.1215x; 1.1215x over previous
#include <cuda_runtime.h>
#include <cuda_bf16.h>
#include <math.h>

#define BB   128     // batch
#define TT   200     // timesteps
#define CC   40      // codes per visit
#define NCODE 2000
#define DAUX 16
#define EE   128     // embedding dim
#define GG   512     // 4*E
#define HH   256     // mlp hidden

// packed f32x2 FMA (SASS FFMA2) — only reachable via PTX
#define FMA2(d, a, b, c) \
    asm("fma.rn.f32x2 %0, %1, %2, %3;" : "=l"(d) : "l"(a), "l"(b), "l"(c))

__device__ __forceinline__ float plo(unsigned long long v) {
    return __uint_as_float((unsigned)v);
}
__device__ __forceinline__ float phi(unsigned long long v) {
    return __uint_as_float((unsigned)(v >> 32));
}

// ---------------- scratch (static device arrays; no runtime allocation) -----
__device__ float g_x [TT * BB * EE];        // relu(embed), row = t*B + b
__device__ float g_xw[TT * BB * GG];        // x @ W_x + b_lstm
__device__ float g_h [(TT + 1) * BB * EE];  // h history, g_h[0] = zeros
__device__ unsigned g_cnt;                  // barrier counter (self-resetting)
__device__ unsigned g_epoch;                // barrier epoch (monotonic)

// ---------------- kernel A: multi-hot embed + aux + bias + relu -------------
__global__ void embed_kernel(const int* __restrict__ code,
                             const float* __restrict__ aux,
                             const float* __restrict__ Wlin,
                             const float* __restrict__ blin) {
    int bt = blockIdx.x;            // b*T + t
    int b = bt / TT, t = bt % TT;
    __shared__ int   codes[CC];
    __shared__ float flags[CC];
    __shared__ float auxs[DAUX];
    int tid = threadIdx.x;          // 128
    if (tid < CC)   codes[tid] = code[bt * CC + tid];
    if (tid < DAUX) auxs[tid]  = aux[bt * DAUX + tid];
    __syncthreads();
    if (tid < CC) {
        int v = codes[tid];
        float f = (v > 0) ? 1.f : 0.f;
        for (int j = 0; j < tid; j++)
            if (codes[j] == v) f = 0.f;   // binary multi-hot: dedupe
        flags[tid] = f;
    }
    __syncthreads();
    float acc = blin[tid];
    #pragma unroll 4
    for (int c = 0; c < CC; c++) {
        if (flags[c] != 0.f)                       // uniform across block
            acc += Wlin[(codes[c] - 1) * EE + tid];
    }
    #pragma unroll
    for (int k = 0; k < DAUX; k++)
        acc += auxs[k] * Wlin[(NCODE + k) * EE + tid];
    g_x[(t * BB + b) * EE + tid] = fmaxf(acc, 0.f);
}

// ---------------- kernel B: xw = x @ W_x + b_lstm  ([25600,128]@[128,512]) --
// 64x64 tile, K chunked by 64, 256 threads, 4x4 micro-tile, f32x2 packed FMA.
// Layouts: xs[r][k], ws[c][k] (both k-contiguous, pad 68) -> LDS.128 along k.
__global__ void __launch_bounds__(256, 1)
xw_kernel(const float* __restrict__ Wx, const float* __restrict__ blstm) {
    __shared__ float xs[64][68];   // [row][k]
    __shared__ float ws[64][68];   // [col][k]
    int tid = threadIdx.x;
    int row0 = blockIdx.x * 64, col0 = blockIdx.y * 64;
    int ty = tid >> 4, tx = tid & 15;   // rows: ty+16i, cols: tx+16j

    unsigned long long acc[4][4];
    #pragma unroll
    for (int i = 0; i < 4; i++)
        #pragma unroll
        for (int j = 0; j < 4; j++) acc[i][j] = 0ull;

    for (int kb = 0; kb < 128; kb += 64) {
        // xs: 64 rows x 64 k, float4 coalesced
        for (int i = tid; i < 64 * 16; i += 256) {
            int r = i >> 4, kq = i & 15;
            *(float4*)&xs[r][kq << 2] =
                *(const float4*)&g_x[(row0 + r) * EE + kb + (kq << 2)];
        }
        // ws: transpose Wx[k][c] -> ws[c][k]
        for (int i = tid; i < 64 * 64; i += 256) {
            int k = i >> 6, c = i & 63;
            ws[c][k] = Wx[(kb + k) * GG + col0 + c];
        }
        __syncthreads();
        #pragma unroll
        for (int k = 0; k < 64; k += 4) {
            ulonglong2 av[4], wv[4];
            #pragma unroll
            for (int i = 0; i < 4; i++)
                av[i] = *(const ulonglong2*)&xs[ty + 16 * i][k];
            #pragma unroll
            for (int j = 0; j < 4; j++)
                wv[j] = *(const ulonglong2*)&ws[tx + 16 * j][k];
            #pragma unroll
            for (int i = 0; i < 4; i++)
                #pragma unroll
                for (int j = 0; j < 4; j++) {
                    FMA2(acc[i][j], av[i].x, wv[j].x, acc[i][j]);
                    FMA2(acc[i][j], av[i].y, wv[j].y, acc[i][j]);
                }
        }
        __syncthreads();
    }
    #pragma unroll
    for (int i = 0; i < 4; i++) {
        int r = row0 + ty + 16 * i;
        #pragma unroll
        for (int j = 0; j < 4; j++) {
            int c = col0 + tx + 16 * j;
            g_xw[r * GG + c] = (plo(acc[i][j]) + phi(acc[i][j])) + blstm[c];
        }
    }
}

// ---------------- kernel C: persistent LSTM with global barrier -------------
// 128 CTAs = 8 b-groups(16) x 16 e-groups(8). CTA computes z columns
// {gate*128 + e0 + el : gate 0..3, el 0..7} (32 cols) for its 16 batch rows.
#define NCTA 128

__device__ __forceinline__ void grid_barrier(unsigned target) {
    __syncthreads();
    if (threadIdx.x == 0) {
        __threadfence();
        unsigned old = atomicAdd(&g_cnt, 1u);
        if (old == NCTA - 1) {
            g_cnt = 0;                       // only this thread is active here
            __threadfence();
            *(volatile unsigned*)&g_epoch = target;   // release
        } else {
            while (*(volatile unsigned*)&g_epoch != target) { }
            __threadfence();
        }
    }
    __syncthreads();
}

__device__ __forceinline__ float sigmoidf_(float x) {
    return 1.f / (1.f + expf(-x));
}

__global__ void __launch_bounds__(256, 1)
lstm_kernel(const float* __restrict__ Wh) {
    int cta = blockIdx.x;
    int bg = cta >> 4;                 // 0..7
    int eg = cta & 15;                 // 0..15
    int b0 = bg * 16, e0 = eg * 8;

    __shared__ float w_sm[32][132];    // [cc][k]   cc = gate*8 + el   (~17 KB)
    __shared__ float h_sm[16][132];    // [b][k]    (~8.4 KB)
    __shared__ float z_sm[16][33];
    __shared__ float c_sm[16][8];      // cell state, persists across steps

    int tid = threadIdx.x;
    unsigned base = *(volatile unsigned*)&g_epoch;  // stable until 1st barrier

    // resident W_h slice, [col][k] layout
    for (int i = tid; i < 32 * 128; i += 256) {
        int cc = i >> 7, k = i & 127;
        int gate = cc >> 3, el = cc & 7;
        w_sm[cc][k] = Wh[k * GG + gate * EE + e0 + el];
    }
    if (tid < 128) c_sm[tid >> 3][tid & 7] = 0.f;
    // cooperative zero of g_h[0]
    {
        int gi = cta * 256 + tid;
        if (gi < BB * EE) g_h[gi] = 0.f;
    }
    unsigned ep = base + 1;
    grid_barrier(ep);

    // warp tiling: 8 warps = 4 col-groups x 2 b-groups
    int lane = tid & 31, w = tid >> 5;
    int cg = w & 3, bgp = w >> 2;
    int cc  = cg * 8 + (lane & 7);               // 0..31
    int bl0 = bgp * 8 + ((lane >> 3) << 1);      // even row of pair
    int bl1 = bl0 + 1;
    int gate = cc >> 3, el = cc & 7;
    int colg = gate * EE + e0 + el;              // column in [0,512)

    const float* wp = w_sm[cc];

    for (int t = 0; t < TT; t++) {
        // load h_t for our 16 batch rows (float4 coalesced)
        const float4* hsrc = (const float4*)&g_h[t * BB * EE + b0 * EE];
        for (int i = tid; i < 16 * 32; i += 256) {
            int r = i >> 5, kq = i & 31;
            *(float4*)&h_sm[r][kq << 2] = hsrc[r * 32 + kq];
        }
        float xw0 = g_xw[(t * BB + b0 + bl0) * GG + colg];
        float xw1 = g_xw[(t * BB + b0 + bl1) * GG + colg];
        __syncthreads();

        unsigned long long accA = 0ull, accB = 0ull;
        const float* h0p = h_sm[bl0];
        const float* h1p = h_sm[bl1];
        #pragma unroll
        for (int k = 0; k < 128; k += 4) {
            ulonglong2 wv = *(const ulonglong2*)(wp + k);
            ulonglong2 h0 = *(const ulonglong2*)(h0p + k);
            ulonglong2 h1 = *(const ulonglong2*)(h1p + k);
            FMA2(accA, h0.x, wv.x, accA);
            FMA2(accB, h1.x, wv.x, accB);
            FMA2(accA, h0.y, wv.y, accA);
            FMA2(accB, h1.y, wv.y, accB);
        }
        z_sm[bl0][cc] = xw0 + (plo(accA) + phi(accA));
        z_sm[bl1][cc] = xw1 + (plo(accB) + phi(accB));
        __syncthreads();

        if (tid < 128) {
            int b2 = tid >> 3, e2 = tid & 7;
            float zi = z_sm[b2][e2];
            float zf = z_sm[b2][8 + e2];
            float zg = z_sm[b2][16 + e2];
            float zo = z_sm[b2][24 + e2];
            float c = sigmoidf_(zf) * c_sm[b2][e2] + sigmoidf_(zi) * tanhf(zg);
            c_sm[b2][e2] = c;
            g_h[(t + 1) * BB * EE + (b0 + b2) * EE + e0 + e2] =
                sigmoidf_(zo) * tanhf(c);
        }
        ep++;
        grid_barrier(ep);    // h_{t+1} fully published
    }
}

// ---------------- kernel D: gather last h, MLP, L2-normalize ----------------
__global__ void __launch_bounds__(256, 1)
head_kernel(const int* __restrict__ length,
            const float* __restrict__ W0,
            const float* __restrict__ b0v,
            const float* __restrict__ W1,
            const float* __restrict__ b1v,
            float* __restrict__ out) {
    int b = blockIdx.x;             // 128
    int tid = threadIdx.x;          // 256
    __shared__ float hl[EE];
    __shared__ float m[HH];
    __shared__ float red[HH];
    int L = length[b];              // 1..200
    if (tid < EE) hl[tid] = g_h[L * BB * EE + b * EE + tid];
    __syncthreads();
    float a0 = b0v[tid], a1 = 0.f, a2 = 0.f, a3 = 0.f;
    #pragma unroll
    for (int k = 0; k < EE; k += 4) {
        a0 = fmaf(hl[k],     W0[(k)     * HH + tid], a0);
        a1 = fmaf(hl[k + 1], W0[(k + 1) * HH + tid], a1);
        a2 = fmaf(hl[k + 2], W0[(k + 2) * HH + tid], a2);
        a3 = fmaf(hl[k + 3], W0[(k + 3) * HH + tid], a3);
    }
    m[tid] = fmaxf((a0 + a1) + (a2 + a3), 0.f);
    __syncthreads();
    float f0 = b1v[tid], f1 = 0.f, f2 = 0.f, f3 = 0.f;
    #pragma unroll
    for (int k = 0; k < HH; k += 4) {
        f0 = fmaf(m[k],     W1[(k)     * HH + tid], f0);
        f1 = fmaf(m[k + 1], W1[(k + 1) * HH + tid], f1);
        f2 = fmaf(m[k + 2], W1[(k + 2) * HH + tid], f2);
        f3 = fmaf(m[k + 3], W1[(k + 3) * HH + tid], f3);
    }
    float f = (f0 + f1) + (f2 + f3);
    red[tid] = f * f;
    __syncthreads();
    for (int s = 128; s > 0; s >>= 1) {
        if (tid < s) red[tid] += red[tid + s];
        __syncthreads();
    }
    out[b * HH + tid] = f / sqrtf(red[0]);
}

// ---------------- launch -----------------------------------------------------
extern "C" void kernel_launch(void* const* d_in, const int* in_sizes, int n_in,
                              void* d_out, int out_size) {
    const int*   code   = (const int*)  d_in[0];
    const float* aux    = (const float*)d_in[1];
    const int*   length = (const int*)  d_in[2];
    // d_in[3] = is_training (unused, inference)
    const float* Wlin   = (const float*)d_in[4];
    const float* blin   = (const float*)d_in[5];
    const float* Wx     = (const float*)d_in[6];
    const float* Wh     = (const float*)d_in[7];
    const float* blstm  = (const float*)d_in[8];
    const float* W0     = (const float*)d_in[9];
    const float* b0v    = (const float*)d_in[10];
    const float* W1     = (const float*)d_in[11];
    const float* b1v    = (const float*)d_in[12];
    float* out = (float*)d_out;

    embed_kernel<<<BB * TT, 128>>>(code, aux, Wlin, blin);
    dim3 gb(TT * BB / 64, GG / 64);
    xw_kernel<<<gb, 256>>>(Wx, blstm);
    lstm_kernel<<<NCTA, 256>>>(Wh);
    head_kernel<<<BB, 256>>>(length, W0, b0v, W1, b1v, out);
}

// round 3
// speedup vs baseline: 2.1417x; 1.9096x over previous
#include <cuda_runtime.h>
#include <cuda_bf16.h>
#include <math.h>

#define BB   128     // batch
#define TT   200     // timesteps
#define CC   40      // codes per visit
#define NCODE 2000
#define DAUX 16
#define EE   128     // embedding dim
#define GG   512     // 4*E
#define HH   256     // mlp hidden

// packed f32x2 FMA (SASS FFMA2) — only reachable via PTX
#define FMA2(d, a, b, c) \
    asm("fma.rn.f32x2 %0, %1, %2, %3;" : "=l"(d) : "l"(a), "l"(b), "l"(c))

__device__ __forceinline__ float plo(unsigned long long v) {
    return __uint_as_float((unsigned)v);
}
__device__ __forceinline__ float phi(unsigned long long v) {
    return __uint_as_float((unsigned)(v >> 32));
}

__device__ __forceinline__ unsigned smem_u32(const void* p) {
    unsigned a;
    asm("{ .reg .u64 t; cvta.to.shared.u64 t, %1; cvt.u32.u64 %0, t; }"
        : "=r"(a) : "l"(p));
    return a;
}

// ---------------- scratch (static device arrays; no runtime allocation) -----
__device__ float g_x   [TT * BB * EE];      // relu(embed), row = t*B + b
__device__ float g_xw  [TT * BB * GG];      // x @ W_x + b_lstm
__device__ float g_last[BB * EE];           // h at last valid timestep per row

// ---------------- kernel A: multi-hot embed + aux + bias + relu -------------
__global__ void embed_kernel(const int* __restrict__ code,
                             const float* __restrict__ aux,
                             const float* __restrict__ Wlin,
                             const float* __restrict__ blin) {
    int bt = blockIdx.x;            // b*T + t
    int b = bt / TT, t = bt % TT;
    __shared__ int   codes[CC];
    __shared__ float flags[CC];
    __shared__ float auxs[DAUX];
    int tid = threadIdx.x;          // 128
    if (tid < CC)   codes[tid] = code[bt * CC + tid];
    if (tid < DAUX) auxs[tid]  = aux[bt * DAUX + tid];
    __syncthreads();
    if (tid < CC) {
        int v = codes[tid];
        float f = (v > 0) ? 1.f : 0.f;
        for (int j = 0; j < tid; j++)
            if (codes[j] == v) f = 0.f;   // binary multi-hot: dedupe
        flags[tid] = f;
    }
    __syncthreads();
    float acc = blin[tid];
    #pragma unroll 4
    for (int c = 0; c < CC; c++) {
        if (flags[c] != 0.f)                       // uniform across block
            acc += Wlin[(codes[c] - 1) * EE + tid];
    }
    #pragma unroll
    for (int k = 0; k < DAUX; k++)
        acc += auxs[k] * Wlin[(NCODE + k) * EE + tid];
    g_x[(t * BB + b) * EE + tid] = fmaxf(acc, 0.f);
}

// ---------------- kernel B: xw = x @ W_x + b_lstm  ([25600,128]@[128,512]) --
__global__ void __launch_bounds__(256, 1)
xw_kernel(const float* __restrict__ Wx, const float* __restrict__ blstm) {
    __shared__ float xs[64][68];   // [row][k]
    __shared__ float ws[64][68];   // [col][k]
    int tid = threadIdx.x;
    int row0 = blockIdx.x * 64, col0 = blockIdx.y * 64;
    int ty = tid >> 4, tx = tid & 15;   // rows: ty+16i, cols: tx+16j

    unsigned long long acc[4][4];
    #pragma unroll
    for (int i = 0; i < 4; i++)
        #pragma unroll
        for (int j = 0; j < 4; j++) acc[i][j] = 0ull;

    for (int kb = 0; kb < 128; kb += 64) {
        for (int i = tid; i < 64 * 16; i += 256) {
            int r = i >> 4, kq = i & 15;
            *(float4*)&xs[r][kq << 2] =
                *(const float4*)&g_x[(row0 + r) * EE + kb + (kq << 2)];
        }
        for (int i = tid; i < 64 * 64; i += 256) {
            int k = i >> 6, c = i & 63;
            ws[c][k] = Wx[(kb + k) * GG + col0 + c];
        }
        __syncthreads();
        #pragma unroll
        for (int k = 0; k < 64; k += 4) {
            ulonglong2 av[4], wv[4];
            #pragma unroll
            for (int i = 0; i < 4; i++)
                av[i] = *(const ulonglong2*)&xs[ty + 16 * i][k];
            #pragma unroll
            for (int j = 0; j < 4; j++)
                wv[j] = *(const ulonglong2*)&ws[tx + 16 * j][k];
            #pragma unroll
            for (int i = 0; i < 4; i++)
                #pragma unroll
                for (int j = 0; j < 4; j++) {
                    FMA2(acc[i][j], av[i].x, wv[j].x, acc[i][j]);
                    FMA2(acc[i][j], av[i].y, wv[j].y, acc[i][j]);
                }
        }
        __syncthreads();
    }
    #pragma unroll
    for (int i = 0; i < 4; i++) {
        int r = row0 + ty + 16 * i;
        #pragma unroll
        for (int j = 0; j < 4; j++) {
            int c = col0 + tx + 16 * j;
            g_xw[r * GG + c] = (plo(acc[i][j]) + phi(acc[i][j])) + blstm[c];
        }
    }
}

// ---------------- kernel C: cluster-synced LSTM ------------------------------
// 32 clusters x 4 CTAs. Cluster owns 4 batch rows; CTA rank owns e-slice
// [32*rank, 32*rank+32) = 128 z-cols (4 gates x 32 e). W_h slice lives in
// registers (128 regs/thread). h exchanged via DSMEM + barrier.cluster.
#define CLUS 4

__device__ __forceinline__ float sigmoidf_(float x) {
    return 1.f / (1.f + expf(-x));
}

__global__ void __launch_bounds__(128, 1) __cluster_dims__(CLUS, 1, 1)
lstm_kernel(const float* __restrict__ Wh, const int* __restrict__ length) {
    __shared__ __align__(16) float h_sm[2][4][EE];   // double-buffered h
    __shared__ float z_sm[4][132];

    int tid = threadIdx.x;                 // 128
    unsigned rank;
    asm("mov.u32 %0, %%cluster_ctarank;" : "=r"(rank));
    int b0 = (blockIdx.x >> 2) * 4;        // 4 batch rows per cluster
    int e0 = rank * 32;
    int gate = tid >> 5, el = tid & 31;
    int colg = gate * EE + e0 + el;        // column in [0, 512)

    // W_h column -> registers (coalesced per k across the warp)
    unsigned long long w_reg[64];
    #pragma unroll
    for (int j = 0; j < 64; j++) {
        float lo = Wh[(2 * j) * GG + colg];
        float hi = Wh[(2 * j + 1) * GG + colg];
        w_reg[j] = (unsigned long long)__float_as_uint(lo) |
                   ((unsigned long long)__float_as_uint(hi) << 32);
    }

    // zero own h buffer 0 (h_0 = 0)
    for (int i = tid; i < 4 * EE; i += 128) (&h_sm[0][0][0])[i] = 0.f;

    // epilogue identity: thread = (row er, e-offset eel)
    int er = tid >> 5, eel = tid & 31;
    int Lrow = length[b0 + er];
    float c_reg = 0.f;

    // peer smem base addresses (mapa)
    unsigned hbase = smem_u32(&h_sm[0][0][0]);
    unsigned peer[CLUS];
    #pragma unroll
    for (int p = 0; p < CLUS; p++)
        asm("mapa.shared::cluster.u32 %0, %1, %2;"
            : "=r"(peer[p]) : "r"(hbase), "r"(p));

    asm volatile("barrier.cluster.arrive.aligned;" ::: "memory");
    asm volatile("barrier.cluster.wait.aligned;" ::: "memory");

    for (int t = 0; t < TT; t++) {
        int buf = t & 1;
        // prefetch xw for our 4 rows (coalesced 128B per warp per row)
        float xwv[4];
        #pragma unroll
        for (int r = 0; r < 4; r++)
            xwv[r] = g_xw[(t * BB + b0 + r) * GG + colg];

        unsigned long long acc[4] = {0ull, 0ull, 0ull, 0ull};
        #pragma unroll
        for (int k4 = 0; k4 < 32; k4++) {
            #pragma unroll
            for (int r = 0; r < 4; r++) {
                ulonglong2 hv = *(const ulonglong2*)&h_sm[buf][r][k4 * 4];
                FMA2(acc[r], hv.x, w_reg[2 * k4],     acc[r]);
                FMA2(acc[r], hv.y, w_reg[2 * k4 + 1], acc[r]);
            }
        }
        #pragma unroll
        for (int r = 0; r < 4; r++)
            z_sm[r][tid] = xwv[r] + (plo(acc[r]) + phi(acc[r]));
        __syncthreads();

        // epilogue: gates for (row er, e = e0+eel)
        float zi = z_sm[er][eel];
        float zf = z_sm[er][32 + eel];
        float zg = z_sm[er][64 + eel];
        float zo = z_sm[er][96 + eel];
        c_reg = sigmoidf_(zf) * c_reg + sigmoidf_(zi) * tanhf(zg);
        float h = sigmoidf_(zo) * tanhf(c_reg);

        // publish h to all cluster CTAs' next buffer (incl. self)
        unsigned off = (((unsigned)(buf ^ 1) * 4 + er) * EE + (e0 + eel)) * 4u;
        #pragma unroll
        for (int p = 0; p < CLUS; p++)
            asm volatile("st.shared::cluster.f32 [%0], %1;"
                         :: "r"(peer[p] + off), "f"(h));
        if (t + 1 == Lrow)
            g_last[(b0 + er) * EE + e0 + eel] = h;

        // cluster barrier: release our DSMEM stores, acquire peers'
        asm volatile("barrier.cluster.arrive.aligned;" ::: "memory");
        asm volatile("barrier.cluster.wait.aligned;" ::: "memory");
    }
}

// ---------------- kernel D: MLP head + L2-normalize --------------------------
__global__ void __launch_bounds__(256, 1)
head_kernel(const float* __restrict__ W0,
            const float* __restrict__ b0v,
            const float* __restrict__ W1,
            const float* __restrict__ b1v,
            float* __restrict__ out) {
    int b = blockIdx.x;             // 128
    int tid = threadIdx.x;          // 256
    __shared__ float hl[EE];
    __shared__ float m[HH];
    __shared__ float red[HH];
    if (tid < EE) hl[tid] = g_last[b * EE + tid];
    __syncthreads();
    float a0 = b0v[tid], a1 = 0.f, a2 = 0.f, a3 = 0.f;
    #pragma unroll
    for (int k = 0; k < EE; k += 4) {
        a0 = fmaf(hl[k],     W0[(k)     * HH + tid], a0);
        a1 = fmaf(hl[k + 1], W0[(k + 1) * HH + tid], a1);
        a2 = fmaf(hl[k + 2], W0[(k + 2) * HH + tid], a2);
        a3 = fmaf(hl[k + 3], W0[(k + 3) * HH + tid], a3);
    }
    m[tid] = fmaxf((a0 + a1) + (a2 + a3), 0.f);
    __syncthreads();
    float f0 = b1v[tid], f1 = 0.f, f2 = 0.f, f3 = 0.f;
    #pragma unroll
    for (int k = 0; k < HH; k += 4) {
        f0 = fmaf(m[k],     W1[(k)     * HH + tid], f0);
        f1 = fmaf(m[k + 1], W1[(k + 1) * HH + tid], f1);
        f2 = fmaf(m[k + 2], W1[(k + 2) * HH + tid], f2);
        f3 = fmaf(m[k + 3], W1[(k + 3) * HH + tid], f3);
    }
    float f = (f0 + f1) + (f2 + f3);
    red[tid] = f * f;
    __syncthreads();
    for (int s = 128; s > 0; s >>= 1) {
        if (tid < s) red[tid] += red[tid + s];
        __syncthreads();
    }
    out[b * HH + tid] = f / sqrtf(red[0]);
}

// ---------------- launch -----------------------------------------------------
extern "C" void kernel_launch(void* const* d_in, const int* in_sizes, int n_in,
                              void* d_out, int out_size) {
    const int*   code   = (const int*)  d_in[0];
    const float* aux    = (const float*)d_in[1];
    const int*   length = (const int*)  d_in[2];
    // d_in[3] = is_training (unused, inference)
    const float* Wlin   = (const float*)d_in[4];
    const float* blin   = (const float*)d_in[5];
    const float* Wx     = (const float*)d_in[6];
    const float* Wh     = (const float*)d_in[7];
    const float* blstm  = (const float*)d_in[8];
    const float* W0     = (const float*)d_in[9];
    const float* b0v    = (const float*)d_in[10];
    const float* W1     = (const float*)d_in[11];
    const float* b1v    = (const float*)d_in[12];
    float* out = (float*)d_out;

    embed_kernel<<<BB * TT, 128>>>(code, aux, Wlin, blin);
    dim3 gb(TT * BB / 64, GG / 64);
    xw_kernel<<<gb, 256>>>(Wx, blstm);
    lstm_kernel<<<BB, 128>>>(Wh, length);   // 32 clusters x 4 CTAs
    head_kernel<<<BB, 256>>>(W0, b0v, W1, b1v, out);
}